// round 6
// baseline (speedup 1.0000x reference)
#include <cuda_runtime.h>
#include <cuda_bf16.h>
#include <cstdint>

// PlatonicLinear == x[524288,192] @ W^T + bias; W fixed 192x192 expanded from A4 group.
// sm_103 baseline (no tcgen05 in this toolchain): warp-level mma.sync bf16 GEMM,
// split-precision (x_hi*W_hi + x_lo*W_hi + x_hi*W_lo, fp32 accumulate).
// R4 fix: B fragments use ldmatrix WITHOUT .trans — W smem is [n][k] (k contiguous),
// which is already col-major B; .trans was transposing each 8x8 block (rel_err 1.34).
// R5: software-pipeline the x tile — next tile's LDGs issue before the MMA mainloop,
// cvt+STS happen after the post-epilogue sync, hiding gmem latency behind HMMAs.
// R6: resubmission (infra timeout; no new evidence to act on).

#define FEAT   192
#define BM     64
#define THREADS 256
#define G_ORD  12
#define NKS    12            // k16 steps over K=192

// smem byte layout
#define SM_WHI  0            // 192*192 bf16, swizzled  (73728 B)
#define SM_WLO  73728
#define SM_XHI  147456       // 64*192 bf16, swizzled   (24576 B)
#define SM_XLO  172032
#define SM_TOTAL 196608

#define XROWB  384           // bytes per 192-bf16 row

__device__ __align__(16) uint16_t g_Whi[FEAT * FEAT];
__device__ __align__(16) uint16_t g_Wlo[FEAT * FEAT];

// 16B-chunk XOR swizzle: chunk c of row r -> keeps 8-chunk blocks, rotates low3 by row
__host__ __device__ __forceinline__ uint32_t swz16(uint32_t row, uint32_t c) {
    return ((c & 24u) | ((c & 7u) ^ (row & 7u))) * 16u;
}

__device__ __forceinline__ uint32_t smem_u32(const void* p) {
    uint32_t a;
    asm("{ .reg .u64 t; cvta.to.shared.u64 t, %1; cvt.u32.u64 %0, t; }" : "=r"(a) : "l"(p));
    return a;
}

// pack (a -> low half, b -> high half) as bf16x2; lo2 = residuals likewise
__device__ __forceinline__ void cvt_split(float a, float b, uint32_t& hi2, uint32_t& lo2) {
    asm("cvt.rn.bf16x2.f32 %0, %1, %2;" : "=r"(hi2) : "f"(b), "f"(a));
    float ha = __uint_as_float(hi2 << 16);
    float hb = __uint_as_float(hi2 & 0xffff0000u);
    asm("cvt.rn.bf16x2.f32 %0, %1, %2;" : "=r"(lo2) : "f"(b - hb), "f"(a - ha));
}

#define LDSM_X4(r0, r1, r2, r3, addr) \
    asm volatile("ldmatrix.sync.aligned.m8n8.x4.shared.b16 {%0,%1,%2,%3}, [%4];" \
                 : "=r"(r0), "=r"(r1), "=r"(r2), "=r"(r3) : "r"(addr))
#define MMA_BF16(c, a0, a1, a2, a3, b0, b1) \
    asm volatile("mma.sync.aligned.m16n8k16.row.col.f32.bf16.bf16.f32 " \
                 "{%0,%1,%2,%3}, {%4,%5,%6,%7}, {%8,%9}, {%0,%1,%2,%3};" \
                 : "+f"((c)[0]), "+f"((c)[1]), "+f"((c)[2]), "+f"((c)[3]) \
                 : "r"(a0), "r"(a1), "r"(a2), "r"(a3), "r"(b0), "r"(b1))

// ---- expand A4 group weight into swizzled bf16 hi/lo, W[f][k] row-major ----
__global__ void build_w_kernel(const float* __restrict__ kern,
                               const int* __restrict__ cayley,
                               const int* __restrict__ inv) {
    int idx = blockIdx.x * blockDim.x + threadIdx.x;
    if (idx >= FEAT * FEAT) return;
    int f = idx / FEAT, k = idx - f * FEAT;
    int h = f >> 4, o = f & 15;
    int g = k >> 4, i = k & 15;
    int kg = cayley[inv[g] * G_ORD + h];
    float w = kern[(kg * 16 + o) * 16 + i];

    __nv_bfloat16 hi = __float2bfloat16(w);
    __nv_bfloat16 lo = __float2bfloat16(w - __bfloat162float(hi));

    uint32_t off = (uint32_t)f * XROWB + swz16((uint32_t)f, (uint32_t)(k >> 3)) + (uint32_t)(k & 7) * 2u;
    g_Whi[off >> 1] = *(const uint16_t*)&hi;
    g_Wlo[off >> 1] = *(const uint16_t*)&lo;
}

__global__ __launch_bounds__(THREADS, 1)
void gemm_kernel(const float* __restrict__ x,
                 const float* __restrict__ bias,
                 float* __restrict__ out,
                 int ntiles) {
    extern __shared__ char smem[];
    const uint32_t sbase = smem_u32(smem);
    const int tid  = threadIdx.x;
    const int wid  = tid >> 5;
    const int lane = tid & 31;

    // ---- copy W hi/lo into smem (already swizzled; raw 16B copy) ----
    {
        const float4* sh = (const float4*)g_Whi;
        const float4* sl = (const float4*)g_Wlo;
        float4* dh = (float4*)(smem + SM_WHI);
        float4* dl = (float4*)(smem + SM_WLO);
        #pragma unroll 4
        for (int i = tid; i < 73728 / 16; i += THREADS) { dh[i] = sh[i]; dl[i] = sl[i]; }
    }

    // ---- warp tiling: 4 m-slabs x 2 n-halves ----
    const int m0    = (wid & 3) * 16;   // rows within tile
    const int nbase = (wid >> 2) * 96;  // feature offset
    const int gr  = lane >> 2;
    const int tig = lane & 3;

    const float b0 = bias[tig * 2];
    const float b1 = bias[tig * 2 + 1];
    const float b2 = bias[tig * 2 + 8];
    const float b3 = bias[tig * 2 + 9];

    // per-lane ldmatrix address components (loop-invariant)
    // A (x tile, [m][k]): lanes 0-15 rows m0..m0+15 chunk +0; lanes 16-31 same rows chunk +1
    //   -> a0=(m0-7,k0-7) a1=(m8-15,k0-7) a2=(m0-7,k8-15) a3=(m8-15,k8-15)  [matches mma A order]
    const uint32_t a_row = (uint32_t)(m0 + (lane & 15));
    const uint32_t a_chx = (uint32_t)(lane >> 4);
    // B (W tile, [n][k], non-trans): m0=(n0-7,k0-7) m1=(n0-7,k8-15) m2=(n8-15,k0-7) m3=(n8-15,k8-15)
    const uint32_t b_rowl = (uint32_t)((lane & 7) + ((lane >> 4) << 3));
    const uint32_t b_chx  = (uint32_t)((lane >> 3) & 1);

    // per-thread x-loader mapping (6 chunks of 8 floats each per thread)
    int ld_row[6], ld_c[6];
    #pragma unroll
    for (int i = 0; i < 6; i++) {
        int idx = tid + i * THREADS;       // 0..1535 over 64 rows x 24 chunks
        ld_row[i] = idx / 24;
        ld_c[i]   = idx - ld_row[i] * 24;
    }

    // ---- prologue: load+convert+store first tile ----
    float4 pf[12];
    {
        const float* xb = x + (size_t)blockIdx.x * BM * FEAT;
        #pragma unroll
        for (int i = 0; i < 6; i++) {
            const float4* p = (const float4*)(xb + ld_row[i] * FEAT + ld_c[i] * 8);
            pf[2 * i] = p[0]; pf[2 * i + 1] = p[1];
        }
        #pragma unroll
        for (int i = 0; i < 6; i++) {
            uint4 hi, lo;
            cvt_split(pf[2 * i].x,     pf[2 * i].y,     hi.x, lo.x);
            cvt_split(pf[2 * i].z,     pf[2 * i].w,     hi.y, lo.y);
            cvt_split(pf[2 * i + 1].x, pf[2 * i + 1].y, hi.z, lo.z);
            cvt_split(pf[2 * i + 1].z, pf[2 * i + 1].w, hi.w, lo.w);
            uint32_t off = (uint32_t)ld_row[i] * XROWB + swz16((uint32_t)ld_row[i], (uint32_t)ld_c[i]);
            *(uint4*)(smem + SM_XHI + off) = hi;
            *(uint4*)(smem + SM_XLO + off) = lo;
        }
    }
    __syncthreads();

    for (int t = blockIdx.x; t < ntiles; t += gridDim.x) {
        const int tn = t + gridDim.x;
        const bool have_next = tn < ntiles;

        // ---- issue next tile's gmem loads (latency hidden behind MMAs) ----
        if (have_next) {
            const float* xb = x + (size_t)tn * BM * FEAT;
            #pragma unroll
            for (int i = 0; i < 6; i++) {
                const float4* p = (const float4*)(xb + ld_row[i] * FEAT + ld_c[i] * 8);
                pf[2 * i] = p[0]; pf[2 * i + 1] = p[1];
            }
        }

        // ---- mma mainloop: 12 k16 steps, 12 n8 tiles/warp, 3 precision passes ----
        float acc[12][4];
        #pragma unroll
        for (int n = 0; n < 12; n++)
            #pragma unroll
            for (int j = 0; j < 4; j++) acc[n][j] = 0.0f;

        #pragma unroll
        for (int ks = 0; ks < NKS; ks++) {
            const uint32_t c = (uint32_t)(ks * 2);

            uint32_t ah0, ah1, ah2, ah3, al0, al1, al2, al3;
            {
                uint32_t off = a_row * XROWB + swz16(a_row, c + a_chx);
                LDSM_X4(ah0, ah1, ah2, ah3, sbase + SM_XHI + off);
                LDSM_X4(al0, al1, al2, al3, sbase + SM_XLO + off);
            }

            #pragma unroll
            for (int nt = 0; nt < 6; nt++) {
                uint32_t brow = (uint32_t)(nbase + nt * 16) + b_rowl;
                uint32_t off  = brow * XROWB + swz16(brow, c + b_chx);
                uint32_t bh0, bh1, bh2, bh3, bl0, bl1, bl2, bl3;
                LDSM_X4(bh0, bh1, bh2, bh3, sbase + SM_WHI + off);
                LDSM_X4(bl0, bl1, bl2, bl3, sbase + SM_WLO + off);

                // interleave the two n8 accumulators to break depth-3 RAW chains
                MMA_BF16(acc[nt * 2],     ah0, ah1, ah2, ah3, bh0, bh1);
                MMA_BF16(acc[nt * 2 + 1], ah0, ah1, ah2, ah3, bh2, bh3);
                MMA_BF16(acc[nt * 2],     al0, al1, al2, al3, bh0, bh1);
                MMA_BF16(acc[nt * 2 + 1], al0, al1, al2, al3, bh2, bh3);
                MMA_BF16(acc[nt * 2],     ah0, ah1, ah2, ah3, bl0, bl1);
                MMA_BF16(acc[nt * 2 + 1], ah0, ah1, ah2, ah3, bl2, bl3);
            }
        }

        // ---- epilogue: bias + float2 stores ----
        {
            float* ob = out + ((size_t)t * BM + m0 + gr) * FEAT + nbase + tig * 2;
            #pragma unroll
            for (int nt = 0; nt < 12; nt++) {
                float ba = (nt & 1) ? b2 : b0;
                float bb = (nt & 1) ? b3 : b1;
                float2 v0 = { acc[nt][0] + ba, acc[nt][1] + bb };
                float2 v1 = { acc[nt][2] + ba, acc[nt][3] + bb };
                *(float2*)(ob + nt * 8)            = v0;
                *(float2*)(ob + nt * 8 + 8 * FEAT) = v1;   // rows gr and gr+8
            }
        }

        __syncthreads();   // all warps finished ldmatrix reads of tile t

        // ---- convert + store next tile into smem ----
        if (have_next) {
            #pragma unroll
            for (int i = 0; i < 6; i++) {
                uint4 hi, lo;
                cvt_split(pf[2 * i].x,     pf[2 * i].y,     hi.x, lo.x);
                cvt_split(pf[2 * i].z,     pf[2 * i].w,     hi.y, lo.y);
                cvt_split(pf[2 * i + 1].x, pf[2 * i + 1].y, hi.z, lo.z);
                cvt_split(pf[2 * i + 1].z, pf[2 * i + 1].w, hi.w, lo.w);
                uint32_t off = (uint32_t)ld_row[i] * XROWB + swz16((uint32_t)ld_row[i], (uint32_t)ld_c[i]);
                *(uint4*)(smem + SM_XHI + off) = hi;
                *(uint4*)(smem + SM_XLO + off) = lo;
            }
            __syncthreads();
        }
    }
}

extern "C" void kernel_launch(void* const* d_in, const int* in_sizes, int n_in,
                              void* d_out, int out_size) {
    const float* x      = (const float*)d_in[0];
    const float* kern   = (const float*)d_in[1];
    const float* bias   = (const float*)d_in[2];
    const int*   cayley = (const int*)d_in[3];
    const int*   inv    = (const int*)d_in[4];
    float*       out    = (float*)d_out;

    const int nrows  = in_sizes[0] / FEAT;   // 524288
    const int ntiles = nrows / BM;           // 8192

    build_w_kernel<<<(FEAT * FEAT + 255) / 256, 256>>>(kern, cayley, inv);

    int nsm = 148;
    cudaDeviceGetAttribute(&nsm, cudaDevAttrMultiProcessorCount, 0);
    int grid = nsm < ntiles ? nsm : ntiles;

    cudaFuncSetAttribute(gemm_kernel, cudaFuncAttributeMaxDynamicSharedMemorySize, SM_TOTAL);
    gemm_kernel<<<grid, THREADS, SM_TOTAL>>>(x, bias, out, ntiles);
}

// round 10
// speedup vs baseline: 1.2985x; 1.2985x over previous
#include <cuda_runtime.h>
#include <cuda_fp16.h>
#include <cstdint>

// PlatonicLinear == x[524288,192] @ W^T + bias; W fixed 192x192 expanded from A4 group.
// R6 passed: 287.3us (3-pass bf16), rel_err 4.5e-6. ncu: L1=79% binding, tensor=66.7%.
// R7: warp retile 4x2 -> 2x4 (per-tile LDS 688KB -> 491KB).
// R10: precision scheme bf16 3-pass -> fp16 2-pass (x = x_hi + x_lo in fp16, W single
// fp16 copy). MMAs/step 36->24, B LDS traffic halved, W smem halved (120KB total).
// Error budget: W fp16 quantization 2^-11 -> predicted rel_err ~2.8e-4 (norm metric,
// model validated by R6's 4.5e-6 == RMS prediction for the 3-pass scheme).

#define FEAT   192
#define BM     64
#define THREADS 256
#define G_ORD  12
#define NKS    12            // k16 steps over K=192

// smem byte layout
#define SM_W    0            // 192*192 fp16, swizzled  (73728 B)
#define SM_XHI  73728        // 64*192 fp16, swizzled   (24576 B)
#define SM_XLO  98304
#define SM_TOTAL 122880

#define XROWB  384           // bytes per 192-fp16 row

__device__ __align__(16) uint16_t g_W[FEAT * FEAT];

// 16B-chunk XOR swizzle: chunk c of row r -> keeps 8-chunk blocks, rotates low3 by row
__host__ __device__ __forceinline__ uint32_t swz16(uint32_t row, uint32_t c) {
    return ((c & 24u) | ((c & 7u) ^ (row & 7u))) * 16u;
}

__device__ __forceinline__ uint32_t smem_u32(const void* p) {
    uint32_t a;
    asm("{ .reg .u64 t; cvta.to.shared.u64 t, %1; cvt.u32.u64 %0, t; }" : "=r"(a) : "l"(p));
    return a;
}

// fp16 split: pack (a -> low half, b -> high half); lo2 = fp16 residuals likewise
__device__ __forceinline__ void cvt_split(float a, float b, uint32_t& hi2, uint32_t& lo2) {
    asm("cvt.rn.f16x2.f32 %0, %1, %2;" : "=r"(hi2) : "f"(b), "f"(a));
    __half2 h2 = *reinterpret_cast<const __half2*>(&hi2);
    float2 hf = __half22float2(h2);          // .x = low = fp16(a), .y = high = fp16(b)
    asm("cvt.rn.f16x2.f32 %0, %1, %2;" : "=r"(lo2) : "f"(b - hf.y), "f"(a - hf.x));
}

#define LDSM_X4(r0, r1, r2, r3, addr) \
    asm volatile("ldmatrix.sync.aligned.m8n8.x4.shared.b16 {%0,%1,%2,%3}, [%4];" \
                 : "=r"(r0), "=r"(r1), "=r"(r2), "=r"(r3) : "r"(addr))
#define MMA_F16(c, a0, a1, a2, a3, b0, b1) \
    asm volatile("mma.sync.aligned.m16n8k16.row.col.f32.f16.f16.f32 " \
                 "{%0,%1,%2,%3}, {%4,%5,%6,%7}, {%8,%9}, {%0,%1,%2,%3};" \
                 : "+f"((c)[0]), "+f"((c)[1]), "+f"((c)[2]), "+f"((c)[3]) \
                 : "r"(a0), "r"(a1), "r"(a2), "r"(a3), "r"(b0), "r"(b1))

// ---- expand A4 group weight into swizzled fp16, W[f][k] row-major ----
__global__ void build_w_kernel(const float* __restrict__ kern,
                               const int* __restrict__ cayley,
                               const int* __restrict__ inv) {
    int idx = blockIdx.x * blockDim.x + threadIdx.x;
    if (idx >= FEAT * FEAT) return;
    int f = idx / FEAT, k = idx - f * FEAT;
    int h = f >> 4, o = f & 15;
    int g = k >> 4, i = k & 15;
    int kg = cayley[inv[g] * G_ORD + h];
    float w = kern[(kg * 16 + o) * 16 + i];

    __half w16 = __float2half_rn(w);

    uint32_t off = (uint32_t)f * XROWB + swz16((uint32_t)f, (uint32_t)(k >> 3)) + (uint32_t)(k & 7) * 2u;
    g_W[off >> 1] = *(const uint16_t*)&w16;
}

__global__ __launch_bounds__(THREADS, 1)
void gemm_kernel(const float* __restrict__ x,
                 const float* __restrict__ bias,
                 float* __restrict__ out,
                 int ntiles) {
    extern __shared__ char smem[];
    const uint32_t sbase = smem_u32(smem);
    const int tid  = threadIdx.x;
    const int wid  = tid >> 5;
    const int lane = tid & 31;

    // ---- copy W into smem (already swizzled; raw 16B copy) ----
    {
        const float4* sw = (const float4*)g_W;
        float4* dw = (float4*)(smem + SM_W);
        #pragma unroll 4
        for (int i = tid; i < 73728 / 16; i += THREADS) dw[i] = sw[i];
    }

    // ---- warp tiling: 2 m-slabs (32 rows) x 4 n-quarters (48 cols) ----
    const int m0    = (wid & 1) * 32;   // rows within tile
    const int nbase = (wid >> 1) * 48;  // feature offset (multiple of 16)
    const int gr  = lane >> 2;
    const int tig = lane & 3;

    const float b0 = bias[tig * 2];
    const float b1 = bias[tig * 2 + 1];
    const float b2 = bias[tig * 2 + 8];
    const float b3 = bias[tig * 2 + 9];

    // per-lane ldmatrix address components (loop-invariant)
    // A (x tile, [m][k]): lanes 0-15 rows +0..15 chunk +0; lanes 16-31 same rows chunk +1
    const uint32_t a_row0 = (uint32_t)(m0 + (lane & 15));        // m-chunk 0
    const uint32_t a_row1 = a_row0 + 16u;                        // m-chunk 1
    const uint32_t a_chx  = (uint32_t)(lane >> 4);
    // B (W tile, [n][k], non-trans): lanes 0-15 rows n+0..7 (chunk +0/+1), 16-31 rows n+8..15
    const uint32_t b_rowl = (uint32_t)((lane & 7) + ((lane >> 4) << 3));
    const uint32_t b_chx  = (uint32_t)((lane >> 3) & 1);

    // per-thread x-loader mapping (6 chunks of 8 floats each per thread)
    int ld_row[6], ld_c[6];
    #pragma unroll
    for (int i = 0; i < 6; i++) {
        int idx = tid + i * THREADS;       // 0..1535 over 64 rows x 24 chunks
        ld_row[i] = idx / 24;
        ld_c[i]   = idx - ld_row[i] * 24;
    }

    // ---- prologue: load+convert+store first tile ----
    float4 pf[12];
    {
        const float* xb = x + (size_t)blockIdx.x * BM * FEAT;
        #pragma unroll
        for (int i = 0; i < 6; i++) {
            const float4* p = (const float4*)(xb + ld_row[i] * FEAT + ld_c[i] * 8);
            pf[2 * i] = p[0]; pf[2 * i + 1] = p[1];
        }
        #pragma unroll
        for (int i = 0; i < 6; i++) {
            uint4 hi, lo;
            cvt_split(pf[2 * i].x,     pf[2 * i].y,     hi.x, lo.x);
            cvt_split(pf[2 * i].z,     pf[2 * i].w,     hi.y, lo.y);
            cvt_split(pf[2 * i + 1].x, pf[2 * i + 1].y, hi.z, lo.z);
            cvt_split(pf[2 * i + 1].z, pf[2 * i + 1].w, hi.w, lo.w);
            uint32_t off = (uint32_t)ld_row[i] * XROWB + swz16((uint32_t)ld_row[i], (uint32_t)ld_c[i]);
            *(uint4*)(smem + SM_XHI + off) = hi;
            *(uint4*)(smem + SM_XLO + off) = lo;
        }
    }
    __syncthreads();

    for (int t = blockIdx.x; t < ntiles; t += gridDim.x) {
        const int tn = t + gridDim.x;
        const bool have_next = tn < ntiles;

        // ---- issue next tile's gmem loads (latency hidden behind MMAs) ----
        if (have_next) {
            const float* xb = x + (size_t)tn * BM * FEAT;
            #pragma unroll
            for (int i = 0; i < 6; i++) {
                const float4* p = (const float4*)(xb + ld_row[i] * FEAT + ld_c[i] * 8);
                pf[2 * i] = p[0]; pf[2 * i + 1] = p[1];
            }
        }

        // ---- mma mainloop: 12 k16 steps; per step: 4 A + 3 B LDSM, 24 MMAs ----
        float acc[2][6][4];
        #pragma unroll
        for (int mc = 0; mc < 2; mc++)
            #pragma unroll
            for (int n = 0; n < 6; n++)
                #pragma unroll
                for (int j = 0; j < 4; j++) acc[mc][n][j] = 0.0f;

        #pragma unroll
        for (int ks = 0; ks < NKS; ks++) {
            const uint32_t c = (uint32_t)(ks * 2);

            uint32_t ah[2][4], al[2][4];
            {
                uint32_t off0 = a_row0 * XROWB + swz16(a_row0, c + a_chx);
                uint32_t off1 = a_row1 * XROWB + swz16(a_row1, c + a_chx);
                LDSM_X4(ah[0][0], ah[0][1], ah[0][2], ah[0][3], sbase + SM_XHI + off0);
                LDSM_X4(al[0][0], al[0][1], al[0][2], al[0][3], sbase + SM_XLO + off0);
                LDSM_X4(ah[1][0], ah[1][1], ah[1][2], ah[1][3], sbase + SM_XHI + off1);
                LDSM_X4(al[1][0], al[1][1], al[1][2], al[1][3], sbase + SM_XLO + off1);
            }

            #pragma unroll
            for (int ng = 0; ng < 3; ng++) {           // 3 n16 groups (48 cols)
                uint32_t brow = (uint32_t)(nbase + ng * 16) + b_rowl;
                uint32_t off  = brow * XROWB + swz16(brow, c + b_chx);
                uint32_t bw0, bw1, bw2, bw3;
                LDSM_X4(bw0, bw1, bw2, bw3, sbase + SM_W + off);

                // 8 MMAs over 4 independent accumulators -> deep interleave
                #pragma unroll
                for (int mc = 0; mc < 2; mc++) {
                    MMA_F16(acc[mc][ng * 2],     ah[mc][0], ah[mc][1], ah[mc][2], ah[mc][3], bw0, bw1);
                    MMA_F16(acc[mc][ng * 2 + 1], ah[mc][0], ah[mc][1], ah[mc][2], ah[mc][3], bw2, bw3);
                }
                #pragma unroll
                for (int mc = 0; mc < 2; mc++) {
                    MMA_F16(acc[mc][ng * 2],     al[mc][0], al[mc][1], al[mc][2], al[mc][3], bw0, bw1);
                    MMA_F16(acc[mc][ng * 2 + 1], al[mc][0], al[mc][1], al[mc][2], al[mc][3], bw2, bw3);
                }
            }
        }

        // ---- epilogue: bias + float2 stores (2 m-chunks x 6 n8 tiles) ----
        #pragma unroll
        for (int mc = 0; mc < 2; mc++) {
            float* ob = out + ((size_t)t * BM + m0 + mc * 16 + gr) * FEAT + nbase + tig * 2;
            #pragma unroll
            for (int nt = 0; nt < 6; nt++) {
                float ba = (nt & 1) ? b2 : b0;
                float bb = (nt & 1) ? b3 : b1;
                float2 v0 = { acc[mc][nt][0] + ba, acc[mc][nt][1] + bb };
                float2 v1 = { acc[mc][nt][2] + ba, acc[mc][nt][3] + bb };
                *(float2*)(ob + nt * 8)            = v0;
                *(float2*)(ob + nt * 8 + 8 * FEAT) = v1;   // rows gr and gr+8
            }
        }

        __syncthreads();   // all warps finished ldmatrix reads of tile t

        // ---- convert + store next tile into smem ----
        if (have_next) {
            #pragma unroll
            for (int i = 0; i < 6; i++) {
                uint4 hi, lo;
                cvt_split(pf[2 * i].x,     pf[2 * i].y,     hi.x, lo.x);
                cvt_split(pf[2 * i].z,     pf[2 * i].w,     hi.y, lo.y);
                cvt_split(pf[2 * i + 1].x, pf[2 * i + 1].y, hi.z, lo.z);
                cvt_split(pf[2 * i + 1].z, pf[2 * i + 1].w, hi.w, lo.w);
                uint32_t off = (uint32_t)ld_row[i] * XROWB + swz16((uint32_t)ld_row[i], (uint32_t)ld_c[i]);
                *(uint4*)(smem + SM_XHI + off) = hi;
                *(uint4*)(smem + SM_XLO + off) = lo;
            }
            __syncthreads();
        }
    }
}

extern "C" void kernel_launch(void* const* d_in, const int* in_sizes, int n_in,
                              void* d_out, int out_size) {
    const float* x      = (const float*)d_in[0];
    const float* kern   = (const float*)d_in[1];
    const float* bias   = (const float*)d_in[2];
    const int*   cayley = (const int*)d_in[3];
    const int*   inv    = (const int*)d_in[4];
    float*       out    = (float*)d_out;

    const int nrows  = in_sizes[0] / FEAT;   // 524288
    const int ntiles = nrows / BM;           // 8192

    build_w_kernel<<<(FEAT * FEAT + 255) / 256, 256>>>(kern, cayley, inv);

    int nsm = 148;
    cudaDeviceGetAttribute(&nsm, cudaDevAttrMultiProcessorCount, 0);
    int grid = nsm < ntiles ? nsm : ntiles;

    cudaFuncSetAttribute(gemm_kernel, cudaFuncAttributeMaxDynamicSharedMemorySize, SM_TOTAL);
    gemm_kernel<<<grid, THREADS, SM_TOTAL>>>(x, bias, out, ntiles);
}

// round 13
// speedup vs baseline: 1.7974x; 1.3842x over previous
#include <cuda_runtime.h>
#include <cuda_fp16.h>
#include <cstdint>

// PlatonicLinear == x[524288,192] @ W^T + bias; W fixed 192x192 expanded from A4 group.
// R10 passed: 221.2us (2-pass fp16 split), rel_err 2.09e-4. ncu: L1=68%, tensor=58%,
// dram=44% — latency-bound, nothing saturated.
// R11: single-pass fp16 (x AND W each rounded once; MMAs/step 24->12, tensor floor
// ~65us) + double-buffered X tile with ONE __syncthreads per tile. Predicted
// rel_err = sqrt(2)*2.09e-4 ~ 3e-4 (x-term mirrors the measured W-term).
// R12/R13: resubmissions (infra timeouts; no new evidence to act on).

#define FEAT   192
#define BM     64
#define THREADS 256
#define G_ORD  12
#define NKS    12            // k16 steps over K=192

// smem byte layout
#define SM_W    0            // 192*192 fp16, swizzled  (73728 B)
#define SM_X0   73728        // 64*192 fp16, swizzled   (24576 B)
#define SM_X1   98304
#define SM_TOTAL 122880

#define XROWB  384           // bytes per 192-fp16 row

__device__ __align__(16) uint16_t g_W[FEAT * FEAT];

// 16B-chunk XOR swizzle: chunk c of row r -> keeps 8-chunk blocks, rotates low3 by row
__host__ __device__ __forceinline__ uint32_t swz16(uint32_t row, uint32_t c) {
    return ((c & 24u) | ((c & 7u) ^ (row & 7u))) * 16u;
}

__device__ __forceinline__ uint32_t smem_u32(const void* p) {
    uint32_t a;
    asm("{ .reg .u64 t; cvta.to.shared.u64 t, %1; cvt.u32.u64 %0, t; }" : "=r"(a) : "l"(p));
    return a;
}

#define LDSM_X4(r0, r1, r2, r3, addr) \
    asm volatile("ldmatrix.sync.aligned.m8n8.x4.shared.b16 {%0,%1,%2,%3}, [%4];" \
                 : "=r"(r0), "=r"(r1), "=r"(r2), "=r"(r3) : "r"(addr))
#define MMA_F16(c, a0, a1, a2, a3, b0, b1) \
    asm volatile("mma.sync.aligned.m16n8k16.row.col.f32.f16.f16.f32 " \
                 "{%0,%1,%2,%3}, {%4,%5,%6,%7}, {%8,%9}, {%0,%1,%2,%3};" \
                 : "+f"((c)[0]), "+f"((c)[1]), "+f"((c)[2]), "+f"((c)[3]) \
                 : "r"(a0), "r"(a1), "r"(a2), "r"(a3), "r"(b0), "r"(b1))

// ---- expand A4 group weight into swizzled fp16, W[f][k] row-major ----
__global__ void build_w_kernel(const float* __restrict__ kern,
                               const int* __restrict__ cayley,
                               const int* __restrict__ inv) {
    int idx = blockIdx.x * blockDim.x + threadIdx.x;
    if (idx >= FEAT * FEAT) return;
    int f = idx / FEAT, k = idx - f * FEAT;
    int h = f >> 4, o = f & 15;
    int g = k >> 4, i = k & 15;
    int kg = cayley[inv[g] * G_ORD + h];
    float w = kern[(kg * 16 + o) * 16 + i];

    __half w16 = __float2half_rn(w);

    uint32_t off = (uint32_t)f * XROWB + swz16((uint32_t)f, (uint32_t)(k >> 3)) + (uint32_t)(k & 7) * 2u;
    g_W[off >> 1] = *(const uint16_t*)&w16;
}

__global__ __launch_bounds__(THREADS, 1)
void gemm_kernel(const float* __restrict__ x,
                 const float* __restrict__ bias,
                 float* __restrict__ out,
                 int ntiles) {
    extern __shared__ char smem[];
    const uint32_t sbase = smem_u32(smem);
    const int tid  = threadIdx.x;
    const int wid  = tid >> 5;
    const int lane = tid & 31;

    // ---- copy W into smem (already swizzled; raw 16B copy) ----
    {
        const float4* sw = (const float4*)g_W;
        float4* dw = (float4*)(smem + SM_W);
        #pragma unroll 4
        for (int i = tid; i < 73728 / 16; i += THREADS) dw[i] = sw[i];
    }

    // ---- warp tiling: 2 m-slabs (32 rows) x 4 n-quarters (48 cols) ----
    const int m0    = (wid & 1) * 32;   // rows within tile
    const int nbase = (wid >> 1) * 48;  // feature offset (multiple of 16)
    const int gr  = lane >> 2;
    const int tig = lane & 3;

    const float b0 = bias[tig * 2];
    const float b1 = bias[tig * 2 + 1];
    const float b2 = bias[tig * 2 + 8];
    const float b3 = bias[tig * 2 + 9];

    // per-lane ldmatrix address components (loop-invariant)
    // A (x tile, [m][k]): lanes 0-15 rows +0..15 chunk +0; lanes 16-31 same rows chunk +1
    const uint32_t a_row0 = (uint32_t)(m0 + (lane & 15));        // m-chunk 0
    const uint32_t a_row1 = a_row0 + 16u;                        // m-chunk 1
    const uint32_t a_chx  = (uint32_t)(lane >> 4);
    // B (W tile, [n][k], non-trans): lanes 0-15 rows n+0..7 (chunk +0/+1), 16-31 rows n+8..15
    const uint32_t b_rowl = (uint32_t)((lane & 7) + ((lane >> 4) << 3));
    const uint32_t b_chx  = (uint32_t)((lane >> 3) & 1);

    // per-thread x-loader mapping (6 chunks of 8 floats each per thread)
    int ld_row[6], ld_c[6];
    uint32_t ld_off[6];
    #pragma unroll
    for (int i = 0; i < 6; i++) {
        int idx = tid + i * THREADS;       // 0..1535 over 64 rows x 24 chunks
        ld_row[i] = idx / 24;
        ld_c[i]   = idx - ld_row[i] * 24;
        ld_off[i] = (uint32_t)ld_row[i] * XROWB + swz16((uint32_t)ld_row[i], (uint32_t)ld_c[i]);
    }

    // ---- prologue: load+convert+store first tile into X0 ----
    float4 pf[12];
    {
        const float* xb = x + (size_t)blockIdx.x * BM * FEAT;
        #pragma unroll
        for (int i = 0; i < 6; i++) {
            const float4* p = (const float4*)(xb + ld_row[i] * FEAT + ld_c[i] * 8);
            pf[2 * i] = p[0]; pf[2 * i + 1] = p[1];
        }
        #pragma unroll
        for (int i = 0; i < 6; i++) {
            uint4 v;
            asm("cvt.rn.f16x2.f32 %0, %1, %2;" : "=r"(v.x) : "f"(pf[2*i].y),     "f"(pf[2*i].x));
            asm("cvt.rn.f16x2.f32 %0, %1, %2;" : "=r"(v.y) : "f"(pf[2*i].w),     "f"(pf[2*i].z));
            asm("cvt.rn.f16x2.f32 %0, %1, %2;" : "=r"(v.z) : "f"(pf[2*i+1].y),   "f"(pf[2*i+1].x));
            asm("cvt.rn.f16x2.f32 %0, %1, %2;" : "=r"(v.w) : "f"(pf[2*i+1].w),   "f"(pf[2*i+1].z));
            *(uint4*)(smem + SM_X0 + ld_off[i]) = v;
        }
    }
    __syncthreads();

    uint32_t xcur = sbase + SM_X0;       // buffer MMAs read this tile
    char*    snxt = smem + SM_X1;        // buffer the convert writes for next tile

    for (int t = blockIdx.x; t < ntiles; t += gridDim.x) {
        const int tn = t + gridDim.x;
        const bool have_next = tn < ntiles;

        // ---- issue next tile's gmem loads (latency hidden behind MMAs) ----
        if (have_next) {
            const float* xb = x + (size_t)tn * BM * FEAT;
            #pragma unroll
            for (int i = 0; i < 6; i++) {
                const float4* p = (const float4*)(xb + ld_row[i] * FEAT + ld_c[i] * 8);
                pf[2 * i] = p[0]; pf[2 * i + 1] = p[1];
            }
        }

        // ---- mma mainloop: 12 k16 steps; per step: 2 A + 3 B LDSM, 12 MMAs ----
        float acc[2][6][4];
        #pragma unroll
        for (int mc = 0; mc < 2; mc++)
            #pragma unroll
            for (int n = 0; n < 6; n++)
                #pragma unroll
                for (int j = 0; j < 4; j++) acc[mc][n][j] = 0.0f;

        #pragma unroll
        for (int ks = 0; ks < NKS; ks++) {
            const uint32_t c = (uint32_t)(ks * 2);

            uint32_t ah[2][4];
            {
                uint32_t off0 = a_row0 * XROWB + swz16(a_row0, c + a_chx);
                uint32_t off1 = a_row1 * XROWB + swz16(a_row1, c + a_chx);
                LDSM_X4(ah[0][0], ah[0][1], ah[0][2], ah[0][3], xcur + off0);
                LDSM_X4(ah[1][0], ah[1][1], ah[1][2], ah[1][3], xcur + off1);
            }

            #pragma unroll
            for (int ng = 0; ng < 3; ng++) {           // 3 n16 groups (48 cols)
                uint32_t brow = (uint32_t)(nbase + ng * 16) + b_rowl;
                uint32_t off  = brow * XROWB + swz16(brow, c + b_chx);
                uint32_t bw0, bw1, bw2, bw3;
                LDSM_X4(bw0, bw1, bw2, bw3, sbase + SM_W + off);

                #pragma unroll
                for (int mc = 0; mc < 2; mc++) {
                    MMA_F16(acc[mc][ng * 2],     ah[mc][0], ah[mc][1], ah[mc][2], ah[mc][3], bw0, bw1);
                    MMA_F16(acc[mc][ng * 2 + 1], ah[mc][0], ah[mc][1], ah[mc][2], ah[mc][3], bw2, bw3);
                }
            }
        }

        // ---- epilogue: bias + float2 stores (2 m-chunks x 6 n8 tiles) ----
        #pragma unroll
        for (int mc = 0; mc < 2; mc++) {
            float* ob = out + ((size_t)t * BM + m0 + mc * 16 + gr) * FEAT + nbase + tig * 2;
            #pragma unroll
            for (int nt = 0; nt < 6; nt++) {
                float ba = (nt & 1) ? b2 : b0;
                float bb = (nt & 1) ? b3 : b1;
                float2 v0 = { acc[mc][nt][0] + ba, acc[mc][nt][1] + bb };
                float2 v1 = { acc[mc][nt][2] + ba, acc[mc][nt][3] + bb };
                *(float2*)(ob + nt * 8)            = v0;
                *(float2*)(ob + nt * 8 + 8 * FEAT) = v1;   // rows gr and gr+8
            }
        }

        // ---- convert + store next tile into the OTHER buffer ----
        // Safe without a pre-barrier: snxt was last READ at tile t-1, whose
        // end-of-tile barrier already ordered those reads before this tile.
        if (have_next) {
            #pragma unroll
            for (int i = 0; i < 6; i++) {
                uint4 v;
                asm("cvt.rn.f16x2.f32 %0, %1, %2;" : "=r"(v.x) : "f"(pf[2*i].y),   "f"(pf[2*i].x));
                asm("cvt.rn.f16x2.f32 %0, %1, %2;" : "=r"(v.y) : "f"(pf[2*i].w),   "f"(pf[2*i].z));
                asm("cvt.rn.f16x2.f32 %0, %1, %2;" : "=r"(v.z) : "f"(pf[2*i+1].y), "f"(pf[2*i+1].x));
                asm("cvt.rn.f16x2.f32 %0, %1, %2;" : "=r"(v.w) : "f"(pf[2*i+1].w), "f"(pf[2*i+1].z));
                *(uint4*)(snxt + ld_off[i]) = v;
            }
            __syncthreads();   // single barrier per tile: publishes snxt, retires xcur reads

            // swap buffers
            uint32_t tmp = xcur;
            xcur = sbase + (uint32_t)(snxt - smem);
            snxt = smem + (tmp - sbase);
        }
    }
}

extern "C" void kernel_launch(void* const* d_in, const int* in_sizes, int n_in,
                              void* d_out, int out_size) {
    const float* x      = (const float*)d_in[0];
    const float* kern   = (const float*)d_in[1];
    const float* bias   = (const float*)d_in[2];
    const int*   cayley = (const int*)d_in[3];
    const int*   inv    = (const int*)d_in[4];
    float*       out    = (float*)d_out;

    const int nrows  = in_sizes[0] / FEAT;   // 524288
    const int ntiles = nrows / BM;           // 8192

    build_w_kernel<<<(FEAT * FEAT + 255) / 256, 256>>>(kern, cayley, inv);

    int nsm = 148;
    cudaDeviceGetAttribute(&nsm, cudaDevAttrMultiProcessorCount, 0);
    int grid = nsm < ntiles ? nsm : ntiles;

    cudaFuncSetAttribute(gemm_kernel, cudaFuncAttributeMaxDynamicSharedMemorySize, SM_TOTAL);
    gemm_kernel<<<grid, THREADS, SM_TOTAL>>>(x, bias, out, ntiles);
}